// round 8
// baseline (speedup 1.0000x reference)
#include <cuda_runtime.h>
#include <math.h>

#define Bq 2
#define Lq 5
#define Cq 64
#define Hq 128
#define Wq 256
#define HWq 32768
#define NHWq 327680
#define OUTQ 4194304

#define NBLK 128           // persistent blocks, 1 per SM (<=148)
#define NTHR 512           // 16 warps: 2 pixel-subtiles x 8 channel-groups
#define PXB  512           // pixels per block = 2 rows of 256

// ---------------- scratch (no allocations; all slots fully overwritten per launch) ----------------
__device__ float        g_sum_r[64][Bq * Cq];   // [slot][b*64+c], single writer each
__device__ float        g_max_r[64][Bq * Cq];
__device__ int          g_cnt_blk[NBLK];
__device__ unsigned int g_arrive;               // monotonic across graph replays

// 5x5 Gaussian, sigma=1: 1/(2*pi*sigma) * exp(-(dx^2+dy^2)/2)  (NOT normalized, matches ref)
__constant__ float GK[25] = {
    0.0029150243f, 0.0130642333f, 0.0215392793f, 0.0130642333f, 0.0029150243f,
    0.0130642333f, 0.0585498315f, 0.0965323526f, 0.0585498315f, 0.0130642333f,
    0.0215392793f, 0.0965323526f, 0.1591549431f, 0.0965323526f, 0.0215392793f,
    0.0130642333f, 0.0585498315f, 0.0965323526f, 0.0585498315f, 0.0130642333f,
    0.0029150243f, 0.0130642333f, 0.0215392793f, 0.0130642333f, 0.0029150243f
};

__device__ __forceinline__ float fsig(float x) { return 1.0f / (1.0f + __expf(-x)); }

// ---- smem layout (bytes) ----
#define TCW 260                         // conf tile cols: -2..257
#define TCH 6                           // conf tile rows: r0-2..r0+3
#define OFF_SC    0                                        // 5*6*260*4 = 31200
#define OFF_MASK  31232                                    // 5*512*4   = 10240
#define OFF_PART  (OFF_MASK + 10240)                       // 2*8*5*32*4= 10240
#define OFF_OUT   (OFF_PART + 10240)                       // 64*512*4  = 131072
#define OFF_PSUM  (OFF_OUT + 131072)                       // 2*64*4    = 512
#define OFF_PMAX  (OFF_PSUM + 512)                         // 2*64*4    = 512
#define OFF_MISC  (OFF_PMAX + 512)                         // enc5 enw5 avg128 mx128 gate64 red128 cnt1
#define SMEM_TOTAL (OFF_MISC + 464 * 4)

__global__ void __launch_bounds__(NTHR, 1) hpha_persistent(
        const float* __restrict__ x,
        const float* __restrict__ psm,
        const float* __restrict__ inv_delay,
        const float* __restrict__ ew_w,
        const float* __restrict__ ew_b,
        const float* __restrict__ ewc_w,
        const float* __restrict__ ewc_b,
        const float* __restrict__ w1,
        const float* __restrict__ w2,
        float* __restrict__ out, int out_size) {
    extern __shared__ char smem[];
    float* sc     = (float*)(smem + OFF_SC);      // [5][6][260]
    float* s_mask = (float*)(smem + OFF_MASK);    // [5][512]
    float* s_part = (float*)(smem + OFF_PART);    // [2][8][5][32]
    float* s_out  = (float*)(smem + OFF_OUT);     // [64][512]
    float* s_psum = (float*)(smem + OFF_PSUM);    // [2][64]
    float* s_pmax = (float*)(smem + OFF_PMAX);    // [2][64]
    float* s_enc  = (float*)(smem + OFF_MISC);          // [5]
    float* s_enw  = s_enc + 5;                          // [5]
    float* s_avg  = s_enw + 5;                          // [128]
    float* s_mx   = s_avg + 128;                        // [128]
    float* s_gate = s_mx + 128;                         // [64]
    int*   s_red  = (int*)(s_gate + 64);                // [128]
    int*   s_cnt  = s_red + 128;                        // [1]

    const int tid  = threadIdx.x;
    const int blk  = blockIdx.x;
    const int b    = blk >> 6;            // batch
    const int s    = blk & 63;            // pixel-range id = private pool slot
    const int P0   = s * PXB;             // first pixel
    const int r0   = s * 2;               // first row (2 rows per block)
    const int lane = tid & 31;
    const int wid  = tid >> 5;
    const int sub  = wid >> 3;            // pixel subtile 0/1
    const int cg   = wid & 7;             // channel group (8 ch)

    // ---------------- phase 0: local mask (never touches DRAM) ----------------
    if (tid < 2 * Lq) {
        int l = tid % Lq;
        float v = tanhf(inv_delay[b * Lq + l] * ((tid < Lq) ? ewc_w[0] : ew_w[0])
                        + ((tid < Lq) ? ewc_b[0] : ew_b[0])) + 1.0f;
        if (tid < Lq) s_enc[l] = v; else s_enw[l] = v;
    }
    if (tid == 0) *s_cnt = 0;
    __syncthreads();

    // conf tile: 5 agents x 6 rows x 260 cols (zero-padded halo)
    for (int idx = tid; idx < Lq * TCH * TCW; idx += NTHR) {
        int l  = idx / (TCH * TCW);
        int r2 = idx - l * (TCH * TCW);
        int tr = r2 / TCW;
        int tc = r2 - tr * TCW;
        int h = r0 - 2 + tr, w = tc - 2;
        float v = 0.0f;
        if (h >= 0 && h < Hq && w >= 0 && w < Wq) {
            int n = b * Lq + l;
            int gi = h * Wq + w;
            float a = psm[(size_t)(n * 2 + 0) * HWq + gi];
            float c = psm[(size_t)(n * 2 + 1) * HWq + gi];
            v = fmaxf(fsig(a), fsig(c)) * s_enc[l];
        }
        sc[idx] = v;
    }
    __syncthreads();

    // 25-tap gaussian -> threshold -> ego -> mask + count (2560 px, 5 per thread, full warps)
    for (int idx = tid; idx < Lq * PXB; idx += NTHR) {
        int l   = idx >> 9;
        int px  = idx & 511;
        int tr  = (px >> 8) + 2;          // row within tile (2 or 3)
        int col = px & 255;
        const float* t = sc + l * (TCH * TCW);
        float acc = 0.0f;
#pragma unroll
        for (int dy = 0; dy < 5; dy++)
#pragma unroll
            for (int dx = 0; dx < 5; dx++)
                acc += GK[dy * 5 + dx] * t[(tr + dy - 2) * TCW + col + dx];
        float m = (acc > 0.01f || l == 0) ? 1.0f : 0.0f;
        s_mask[idx] = m;
        unsigned bal = __ballot_sync(0xffffffffu, m > 0.5f);
        if (lane == 0) atomicAdd(s_cnt, __popc(bal));
    }
    __syncthreads();
    if (tid == 0) g_cnt_blk[blk] = *s_cnt;

    // ---------------- phase 1: fuse into smem, pools in registers ----------------
    float psum[8], pmax[8];
#pragma unroll
    for (int c = 0; c < 8; c++) { psum[c] = 0.0f; pmax[c] = -INFINITY; }

    float* my_part = s_part + ((sub * 8 + cg) * Lq) * 32;
    const float* xbase = x + ((size_t)(b * Lq) * Cq + cg * 8) * HWq + P0;

    for (int it = 0; it < 8; it++) {
        int pxl = it * 64 + sub * 32 + lane;          // pixel within block

        float mk[Lq];
#pragma unroll
        for (int l = 0; l < Lq; l++) mk[l] = s_mask[l * PXB + pxl];

        float xv[8][Lq];
#pragma unroll
        for (int c = 0; c < 8; c++)
#pragma unroll
            for (int l = 0; l < Lq; l++)
                xv[c][l] = xbase[((size_t)l * Cq + c) * HWq + pxl];

        float pd[Lq] = {0.f, 0.f, 0.f, 0.f, 0.f};
#pragma unroll
        for (int c = 0; c < 8; c++) {
            float e = xv[c][0];
#pragma unroll
            for (int l = 0; l < Lq; l++) pd[l] += e * xv[c][l];
        }
#pragma unroll
        for (int l = 0; l < Lq; l++) my_part[l * 32 + lane] = pd[l];
        __syncthreads();

        float dot[Lq];
#pragma unroll
        for (int l = 0; l < Lq; l++) {
            float t = 0.0f;
#pragma unroll
            for (int g = 0; g < 8; g++)
                t += s_part[((sub * 8 + g) * Lq + l) * 32 + lane];
            dot[l] = t;
        }

        float sl[Lq];
#pragma unroll
        for (int l = 0; l < Lq; l++) sl[l] = s_enw[l] * mk[l];

        float scv[Lq], mxv = -INFINITY;
#pragma unroll
        for (int l = 0; l < Lq; l++) {
            scv[l] = dot[l] * sl[0] * sl[l] * 0.125f;   // 1/sqrt(64)
            mxv = fmaxf(mxv, scv[l]);
        }
        float esum = 0.0f;
#pragma unroll
        for (int l = 0; l < Lq; l++) { scv[l] = __expf(scv[l] - mxv); esum += scv[l]; }
        float inv = 1.0f / esum;
        float coef[Lq];
#pragma unroll
        for (int l = 0; l < Lq; l++) coef[l] = scv[l] * inv * sl[l];

#pragma unroll
        for (int c = 0; c < 8; c++) {
            float f = 0.0f;
#pragma unroll
            for (int l = 0; l < Lq; l++) f += coef[l] * xv[c][l];
            s_out[(cg * 8 + c) * PXB + pxl] = f;
            psum[c] += f;
            pmax[c] = fmaxf(pmax[c], f);
        }
        __syncthreads();                                // protect s_part for next iter
    }

    // pool: warp reduce -> per-sub smem -> private global slot (plain stores)
#pragma unroll
    for (int c = 0; c < 8; c++) {
#pragma unroll
        for (int o = 16; o > 0; o >>= 1) {
            psum[c] += __shfl_xor_sync(0xffffffffu, psum[c], o);
            pmax[c] = fmaxf(pmax[c], __shfl_xor_sync(0xffffffffu, pmax[c], o));
        }
    }
    if (lane < 8) {   // lane c stores channel... use lane0 store all 8 (simple, cheap)
    }
    if (lane == 0) {
#pragma unroll
        for (int c = 0; c < 8; c++) {
            s_psum[sub * 64 + cg * 8 + c] = psum[c];
            s_pmax[sub * 64 + cg * 8 + c] = pmax[c];
        }
    }
    __syncthreads();
    if (tid < Cq) {
        g_sum_r[s][b * Cq + tid] = s_psum[tid] + s_psum[64 + tid];
        g_max_r[s][b * Cq + tid] = fmaxf(s_pmax[tid], s_pmax[64 + tid]);
    }

    // ---------------- grid barrier (replay-safe, no resets) ----------------
    if (tid == 0) {
        __threadfence();
        unsigned v = atomicAdd(&g_arrive, 1u);
        unsigned target = (v & ~127u) + 128u;
        unsigned cur;
        do {
            asm volatile("ld.acquire.gpu.u32 %0, [%1];" : "=r"(cur) : "l"(&g_arrive));
        } while (cur < target);
    }
    __syncthreads();

    // ---------------- phase 2: gate MLP + comm_rate + scale from smem ----------------
    if (tid < Bq * Cq) {
        float a = 0.0f, m = -INFINITY;
#pragma unroll 8
        for (int k = 0; k < 64; k++) {
            a += __ldcg(&g_sum_r[k][tid]);
            m = fmaxf(m, __ldcg(&g_max_r[k][tid]));
        }
        s_avg[tid] = a * (1.0f / HWq);
        s_mx[tid]  = m;
    } else if (tid < Bq * Cq + NBLK) {
        s_red[tid - Bq * Cq] = __ldcg(&g_cnt_blk[tid - Bq * Cq]);
    }
    __syncthreads();

    if (tid < Cq) {
        float og = 0.0f;
#pragma unroll
        for (int j = 0; j < 4; j++) {
            float sa = 0.0f, sm = 0.0f;
            for (int cc = 0; cc < Cq; cc++) {
                float w = w1[j * Cq + cc];
                sa += s_avg[b * Cq + cc] * w;
                sm += s_mx[b * Cq + cc] * w;
            }
            og += (fmaxf(sa, 0.0f) + fmaxf(sm, 0.0f)) * w2[tid * 4 + j];
        }
        s_gate[tid] = 1.0f / (1.0f + expf(-og));
    }
    if (blk == 0 && tid >= 256 && tid < 384) {
        // tree-reduce the 128 block counts (threads 256..383 map to s_red)
    }
    __syncthreads();

    if (blk == 0 && tid == 0) {
        int t = 0;
#pragma unroll 8
        for (int k = 0; k < NBLK; k++) t += s_red[k];
        if (out_size > OUTQ) out[OUTQ] = (float)t / (float)NHWq;
    }

    // scale + single write of out
    const float4* so4 = (const float4*)s_out;
    float4* ob4 = (float4*)(out + (size_t)b * Cq * HWq + P0);
    for (int k = tid; k < Cq * PXB / 4; k += NTHR) {
        int c   = k >> 7;                 // 128 float4 per channel
        int off = k & 127;
        float4 v = so4[k];
        float g = s_gate[c];
        v.x *= g; v.y *= g; v.z *= g; v.w *= g;
        ob4[((size_t)c * HWq) / 4 + off] = v;
    }
}

// ---------------- launch ----------------
extern "C" void kernel_launch(void* const* d_in, const int* in_sizes, int n_in,
                              void* d_out, int out_size) {
    const float* x         = (const float*)d_in[0];
    const float* psm       = (const float*)d_in[1];
    const float* inv_delay = (const float*)d_in[2];
    const float* ew_w      = (const float*)d_in[3];
    const float* ew_b      = (const float*)d_in[4];
    const float* ewc_w     = (const float*)d_in[5];
    const float* ewc_b     = (const float*)d_in[6];
    const float* sta_w1    = (const float*)d_in[7];
    const float* sta_w2    = (const float*)d_in[8];
    float* out = (float*)d_out;

    cudaFuncSetAttribute(hpha_persistent,
                         cudaFuncAttributeMaxDynamicSharedMemorySize, SMEM_TOTAL);
    hpha_persistent<<<NBLK, NTHR, SMEM_TOTAL>>>(
        x, psm, inv_delay, ew_w, ew_b, ewc_w, ewc_b, sta_w1, sta_w2, out, out_size);
}